// round 16
// baseline (speedup 1.0000x reference)
#include <cuda_runtime.h>
#include <cuda_bf16.h>
#include <math.h>
#include <stdint.h>

// ---------------- problem constants ----------------
#define B_   2
#define T_   1024
#define NT_  30
#define H_   1024
#define L_   8
#define F_   2816
#define NH_  16
#define HD_  64
#define R_   16
#define M_   (B_*T_)                 // 2048 tokens
#define MH_  ((size_t)M_*H_)
#define HH_  ((size_t)H_*H_)
#define HF_  ((size_t)H_*F_)
#define MF_  ((size_t)M_*F_)

// ---------------- scratch (device globals: no allocation allowed) ----------------
__device__ float g_h  [M_*H_];       // fp32 residual stream
__device__ float g_hn [M_*H_];       // fp32 rms out (head input)
__device__ float g_qkv[3*M_*H_];     // qkv; later Wo split-K partials (2*MH)
__device__ float g_gu [2*M_*F_];     // gu;  later Wd split-K partials (2*MH)
// bf16 hi/lo activation operands
__device__ __nv_bfloat16 g_hn_hi [M_*H_], g_hn_lo [M_*H_];
__device__ __nv_bfloat16 g_att_hi[M_*H_], g_att_lo[M_*H_];
__device__ __nv_bfloat16 g_act_hi[M_*F_], g_act_lo[M_*F_];
// per-head attention operands: Q,K [bh][t][hd]; VT [bh][hd][t]
#define BH_  (B_*NH_)
#define QKN_ ((size_t)BH_*T_*HD_)
__device__ __nv_bfloat16 g_qr_hi[QKN_], g_qr_lo[QKN_];
__device__ __nv_bfloat16 g_kr_hi[QKN_], g_kr_lo[QKN_];
__device__ __nv_bfloat16 g_vt_hi[QKN_], g_vt_lo[QKN_];
// fused+TRANSPOSED effective weights as bf16 hi/lo: W_T[n][k]
__device__ __nv_bfloat16 g_Wq_hi [L_*3*H_*H_], g_Wq_lo [L_*3*H_*H_];
__device__ __nv_bfloat16 g_Wo_hi [L_*H_*H_],   g_Wo_lo [L_*H_*H_];
__device__ __nv_bfloat16 g_Wgu_hi[L_*2*H_*F_], g_Wgu_lo[L_*2*H_*F_];
__device__ __nv_bfloat16 g_Wd_hi [L_*F_*H_],   g_Wd_lo [L_*F_*H_];

// ---------------- helpers ----------------
__device__ __forceinline__ uint32_t s2u(const void* p) {
    uint32_t a;
    asm("{ .reg .u64 t; cvta.to.shared.u64 t, %1; cvt.u32.u64 %0, t; }" : "=r"(a) : "l"(p));
    return a;
}
__device__ __forceinline__ void bsplit(float v, __nv_bfloat16& h, __nv_bfloat16& l) {
    h = __float2bfloat16(v);
    l = __float2bfloat16(v - __bfloat162float(h));
}
__device__ __forceinline__ void cpa16(uint32_t s, const void* g) {
    asm volatile("cp.async.ca.shared.global [%0], [%1], 16;" :: "r"(s), "l"(g) : "memory");
}
__device__ __forceinline__ void cp_commit() {
    asm volatile("cp.async.commit_group;" ::: "memory");
}
template<int NN> __device__ __forceinline__ void cp_wait() {
    asm volatile("cp.async.wait_group %0;" :: "n"(NN) : "memory");
}
__device__ __forceinline__ void mma16816(float* c, const uint32_t* a, const uint32_t* b) {
    asm volatile("mma.sync.aligned.m16n8k16.row.col.f32.bf16.bf16.f32 "
        "{%0,%1,%2,%3}, {%4,%5,%6,%7}, {%8,%9}, {%0,%1,%2,%3};"
        : "+f"(c[0]), "+f"(c[1]), "+f"(c[2]), "+f"(c[3])
        : "r"(a[0]), "r"(a[1]), "r"(a[2]), "r"(a[3]), "r"(b[0]), "r"(b[1]));
}
__device__ __forceinline__ void ldm_x4(uint32_t* r, uint32_t addr) {
    asm volatile("ldmatrix.sync.aligned.m8n8.x4.shared.b16 {%0,%1,%2,%3}, [%4];"
        : "=r"(r[0]), "=r"(r[1]), "=r"(r[2]), "=r"(r[3]) : "r"(addr));
}
__device__ __forceinline__ uint32_t bf2u(__nv_bfloat16 a, __nv_bfloat16 b) {
    uint16_t ua = *reinterpret_cast<uint16_t*>(&a);
    uint16_t ub = *reinterpret_cast<uint16_t*>(&b);
    return (uint32_t)ua | ((uint32_t)ub << 16);
}
__device__ __forceinline__ uint32_t pack_hi(float x, float y, float& rx, float& ry) {
    __nv_bfloat16 hx = __float2bfloat16(x), hy = __float2bfloat16(y);
    rx = x - __bfloat162float(hx);
    ry = y - __bfloat162float(hy);
    return bf2u(hx, hy);
}
__device__ __forceinline__ uint32_t pack_lo(float x, float y) {
    return bf2u(__float2bfloat16(x), __float2bfloat16(y));
}

// ============ bf16x3 tensor-core GEMM: C[M,N] = A @ B^T (slice of K) ============
#define OPT_B   8192u
#define STAGE_B 32768u
#define NSTG    3
#define GSMEM_BYTES (NSTG*STAGE_B)   // 98304

__global__ void __launch_bounds__(128)
gemm_bf16x3(const __nv_bfloat16* __restrict__ Ahi, const __nv_bfloat16* __restrict__ Alo,
            const __nv_bfloat16* __restrict__ Bhi, const __nv_bfloat16* __restrict__ Blo,
            float* __restrict__ C, int N, int Klen, int lda,
            size_t strideB, size_t strideC, int kOffPerZ)
{
    extern __shared__ uint32_t smu[];
    const int kOff = (int)blockIdx.z * kOffPerZ;
    Bhi += (size_t)blockIdx.z * strideB;
    Blo += (size_t)blockIdx.z * strideB;
    C   += (size_t)blockIdx.z * strideC;

    const int tid  = threadIdx.x;
    const int lane = tid & 31;
    const int wid  = tid >> 5;
    const int g    = lane >> 2;
    const int tg   = lane & 3;
    const int rbase = (wid & 1) * 64;
    const int cbase = (wid >> 1) * 64;
    const int row0 = blockIdx.y * 128;
    const int col0 = blockIdx.x * 128;

    const uint32_t smb = s2u(smu);
    const int ld_m  = tid >> 2;
    const int ld_kc = tid & 3;

    auto load_stage = [&](int st, int ch) {
        const uint32_t base = smb + (uint32_t)st * STAGE_B;
        #pragma unroll
        for (int u = 0; u < 4; u++) {
            const int m = ld_m + u * 32;
            const uint32_t sw = (uint32_t)((m * 4 + (ld_kc ^ ((m >> 1) & 3))) << 4);
            const size_t ga = (size_t)(row0 + m) * lda + kOff + ch * 32 + ld_kc * 8;
            const size_t gb = (size_t)(col0 + m) * lda + kOff + ch * 32 + ld_kc * 8;
            cpa16(base +            sw, Ahi + ga);
            cpa16(base + OPT_B    + sw, Alo + ga);
            cpa16(base + 2*OPT_B  + sw, Bhi + gb);
            cpa16(base + 3*OPT_B  + sw, Blo + gb);
        }
        cp_commit();
    };

    const int li = lane & 7;
    const uint32_t aRowBase = (uint32_t)(rbase + li + ((lane >> 3) & 1) * 8);
    const uint32_t aKcSel   = (uint32_t)(lane >> 4);
    const uint32_t bN0      = (uint32_t)(cbase + li + ((lane >> 4) << 3));
    const uint32_t bKcSel   = (uint32_t)((lane >> 3) & 1);
    const uint32_t bXor     = (bN0 >> 1) & 3u;

    float acc[4][8][4];
    #pragma unroll
    for (int mt = 0; mt < 4; mt++)
        #pragma unroll
        for (int nt = 0; nt < 8; nt++)
            #pragma unroll
            for (int c = 0; c < 4; c++) acc[mt][nt][c] = 0.f;

    const int nch = Klen / 32;
    load_stage(0, 0);
    load_stage(1, 1);

    for (int ch = 0; ch < nch; ch++) {
        const int st = ch % NSTG;
        if (ch < nch - 1) cp_wait<1>();
        else              cp_wait<0>();
        __syncthreads();
        if (ch + 2 < nch) load_stage((ch + 2) % NSTG, ch + 2);

        const uint32_t sbase = smb + (uint32_t)st * STAGE_B;
        #pragma unroll
        for (int ks = 0; ks < 2; ks++) {
            uint32_t bh[8][2], bl[8][2];
            {
                const uint32_t bkc = (uint32_t)(ks * 2) + bKcSel;
                const uint32_t a0 = sbase + 2*OPT_B + ((bN0 * 4u + (bkc ^ bXor)) << 4);
                #pragma unroll
                for (int gg = 0; gg < 4; gg++) {
                    uint32_t r[4];
                    ldm_x4(r, a0 + (uint32_t)(gg * 1024));
                    bh[gg*2+0][0]=r[0]; bh[gg*2+0][1]=r[1];
                    bh[gg*2+1][0]=r[2]; bh[gg*2+1][1]=r[3];
                    ldm_x4(r, a0 + OPT_B + (uint32_t)(gg * 1024));
                    bl[gg*2+0][0]=r[0]; bl[gg*2+0][1]=r[1];
                    bl[gg*2+1][0]=r[2]; bl[gg*2+1][1]=r[3];
                }
            }
            #pragma unroll
            for (int mt = 0; mt < 4; mt++) {
                const uint32_t arow = aRowBase + (uint32_t)(mt * 16);
                const uint32_t akc  = (uint32_t)(ks * 2) + aKcSel;
                const uint32_t aH = sbase + ((arow * 4u + (akc ^ ((arow >> 1) & 3u))) << 4);
                uint32_t ah[4], al[4];
                ldm_x4(ah, aH);
                ldm_x4(al, aH + OPT_B);
                #pragma unroll
                for (int nt = 0; nt < 8; nt++) {
                    mma16816(acc[mt][nt], ah, bh[nt]);
                    mma16816(acc[mt][nt], ah, bl[nt]);
                    mma16816(acc[mt][nt], al, bh[nt]);
                }
            }
        }
        // NOTE: no trailing __syncthreads needed with 3 stages:
        // the next overwrite of stage ch happens only after the leading
        // barrier of iteration ch+1, by which point all warps finished
        // reading stage ch.
    }

    #pragma unroll
    for (int mt = 0; mt < 4; mt++) {
        #pragma unroll
        for (int nt = 0; nt < 8; nt++) {
            const int row = row0 + rbase + mt * 16 + g;
            const int col = col0 + cbase + nt * 8 + 2 * tg;
            *(float2*)(C + (size_t)row * N + col)       = make_float2(acc[mt][nt][0], acc[mt][nt][1]);
            *(float2*)(C + (size_t)(row + 8) * N + col) = make_float2(acc[mt][nt][2], acc[mt][nt][3]);
        }
    }
}

// ---------------- LoRA fold: WeffT[n][k] (bf16 hi/lo) ----------------
__global__ void fold_kernel(const float* __restrict__ W, const float* __restrict__ A,
                            const float* __restrict__ Bm,
                            __nv_bfloat16* __restrict__ Whi, __nv_bfloat16* __restrict__ Wlo,
                            int KK, int N) {
    const int mat = blockIdx.z;
    const int i0 = blockIdx.x * 32, j0 = blockIdx.y * 32;
    W   += (size_t)mat * KK * N;
    A   += (size_t)mat * R_ * KK;
    Bm  += (size_t)mat * N * R_;
    Whi += (size_t)mat * (size_t)KK * N;
    Wlo += (size_t)mat * (size_t)KK * N;

    __shared__ float Wt[32][33];
    __shared__ float As[R_][33];
    __shared__ __align__(16) float Bs[32][20];
    const int tx = threadIdx.x & 31, ty = threadIdx.x >> 5;
    #pragma unroll
    for (int u = 0; u < 4; u++) {
        int ii = ty * 4 + u;
        Wt[ii][tx] = W[(size_t)(i0 + ii) * N + j0 + tx];
    }
    #pragma unroll
    for (int u = 0; u < 2; u++) {
        int id = threadIdx.x + u * 256;
        As[id >> 5][id & 31] = A[(size_t)(id >> 5) * KK + i0 + (id & 31)];
    }
    #pragma unroll
    for (int u = 0; u < 2; u++) {
        int id = threadIdx.x + u * 256;
        Bs[id >> 4][id & 15] = Bm[(size_t)(j0 + (id >> 4)) * R_ + (id & 15)];
    }
    __syncthreads();
    float av[R_];
    #pragma unroll
    for (int r = 0; r < R_; r++) av[r] = As[r][tx];
    #pragma unroll
    for (int u = 0; u < 4; u++) {
        int jj = ty * 4 + u;
        float4 b0 = *(const float4*)&Bs[jj][0];
        float4 b1 = *(const float4*)&Bs[jj][4];
        float4 b2 = *(const float4*)&Bs[jj][8];
        float4 b3 = *(const float4*)&Bs[jj][12];
        float bv[R_] = {b0.x,b0.y,b0.z,b0.w, b1.x,b1.y,b1.z,b1.w,
                        b2.x,b2.y,b2.z,b2.w, b3.x,b3.y,b3.z,b3.w};
        float s = 0.f;
        #pragma unroll
        for (int r = 0; r < R_; r++) s += av[r] * bv[r];
        float v = Wt[tx][jj] + 2.0f * s;
        __nv_bfloat16 h, l; bsplit(v, h, l);
        size_t off = (size_t)(j0 + jj) * KK + i0 + tx;
        Whi[off] = h; Wlo[off] = l;
    }
}

// ---------------- h = x @ state_W + state_b ----------------
__global__ void init_h_kernel(const float* __restrict__ x, const float* __restrict__ W,
                              const float* __restrict__ b) {
    const int m = blockIdx.y;
    const int j = blockIdx.x*256 + threadIdx.x;
    __shared__ float xs[NT_];
    if (threadIdx.x < NT_) xs[threadIdx.x] = x[(size_t)m*NT_ + threadIdx.x];
    __syncthreads();
    float s = b[j];
    #pragma unroll
    for (int k = 0; k < NT_; k++) s += xs[k]*W[(size_t)k*H_ + j];
    g_h[(size_t)m*H_ + j] = s;
}

// ---------------- RMSNorm (plain) ----------------
__global__ void rms_kernel(const float* __restrict__ in, const float* __restrict__ w,
                           float* __restrict__ out,
                           __nv_bfloat16* __restrict__ ohi, __nv_bfloat16* __restrict__ olo) {
    const int m = blockIdx.x;
    const float* row = in + (size_t)m*H_;
    float s = 0.f;
    for (int i = threadIdx.x; i < H_; i += 256) { float v = row[i]; s += v*v; }
    __shared__ float red[8];
    #pragma unroll
    for (int o = 16; o; o >>= 1) s += __shfl_xor_sync(0xffffffffu, s, o);
    if ((threadIdx.x & 31) == 0) red[threadIdx.x >> 5] = s;
    __syncthreads();
    if (threadIdx.x < 8) {
        float v = red[threadIdx.x];
        #pragma unroll
        for (int o = 4; o; o >>= 1) v += __shfl_xor_sync(0xffu, v, o);
        if (threadIdx.x == 0) red[0] = v;
    }
    __syncthreads();
    const float inv = rsqrtf(red[0]*(1.0f/H_) + 1e-6f);
    for (int i = threadIdx.x; i < H_; i += 256) {
        float v = row[i]*inv*w[i];
        out[(size_t)m*H_ + i] = v;
        __nv_bfloat16 h, l; bsplit(v, h, l);
        ohi[(size_t)m*H_ + i] = h;
        olo[(size_t)m*H_ + i] = l;
    }
}

// ---------------- fused: h += P0 + P1; rms(h) ----------------
__global__ void rms3_kernel(float* __restrict__ hbuf,
                            const float* __restrict__ P0, const float* __restrict__ P1,
                            const float* __restrict__ w,
                            float* __restrict__ out,
                            __nv_bfloat16* __restrict__ ohi, __nv_bfloat16* __restrict__ olo) {
    const int m = blockIdx.x;
    const size_t base = (size_t)m * H_;
    float v4[4];
    float s = 0.f;
    #pragma unroll
    for (int u = 0; u < 4; u++) {
        const int i = threadIdx.x + u * 256;
        float v = hbuf[base + i] + P0[base + i] + P1[base + i];
        v4[u] = v;
        s += v * v;
        hbuf[base + i] = v;
    }
    __shared__ float red[8];
    #pragma unroll
    for (int o = 16; o; o >>= 1) s += __shfl_xor_sync(0xffffffffu, s, o);
    if ((threadIdx.x & 31) == 0) red[threadIdx.x >> 5] = s;
    __syncthreads();
    if (threadIdx.x < 8) {
        float v = red[threadIdx.x];
        #pragma unroll
        for (int o = 4; o; o >>= 1) v += __shfl_xor_sync(0xffu, v, o);
        if (threadIdx.x == 0) red[0] = v;
    }
    __syncthreads();
    const float inv = rsqrtf(red[0]*(1.0f/H_) + 1e-6f);
    #pragma unroll
    for (int u = 0; u < 4; u++) {
        const int i = threadIdx.x + u * 256;
        float v = v4[u] * inv * w[i];
        out[base + i] = v;
        __nv_bfloat16 h, l; bsplit(v, h, l);
        ohi[base + i] = h;
        olo[base + i] = l;
    }
}

// ---------------- qkv prep: rope(Q,K) + bf16 hi/lo, V transposed ----------------
__global__ void qkv_prep(const float* __restrict__ qkv,
                         __nv_bfloat16* __restrict__ Qh, __nv_bfloat16* __restrict__ Ql,
                         __nv_bfloat16* __restrict__ Kh, __nv_bfloat16* __restrict__ Kl,
                         __nv_bfloat16* __restrict__ Vh, __nv_bfloat16* __restrict__ Vl) {
    const int t0 = blockIdx.x * 64, nh = blockIdx.y, b = blockIdx.z;
    const int bh = b * NH_ + nh;
    const int tid = threadIdx.x;
    __shared__ __nv_bfloat16 vh_s[64][65], vl_s[64][65];
    #pragma unroll
    for (int u = 0; u < 8; u++) {
        const int idx = tid + u * 256;            // 64 rows x 32 freqs
        const int r = idx >> 5, i = idx & 31;
        const int t = t0 + r;
        const size_t gin  = (size_t)(b*T_ + t) * H_ + nh * HD_;
        const size_t gout = ((size_t)bh * T_ + t) * HD_;
        const float inv = expf(-(float)i * (1.0f/32.0f) * 9.210340371976184f);
        const float ang = (float)t * inv;
        const float c = cosf(ang), sn = sinf(ang);
        const float q1 = qkv[gin + i],       q2 = qkv[gin + i + 32];
        const float k1 = qkv[MH_ + gin + i], k2 = qkv[MH_ + gin + i + 32];
        __nv_bfloat16 h, l;
        bsplit(q1*c - q2*sn, h, l); Qh[gout + i]      = h; Ql[gout + i]      = l;
        bsplit(q2*c + q1*sn, h, l); Qh[gout + i + 32] = h; Ql[gout + i + 32] = l;
        bsplit(k1*c - k2*sn, h, l); Kh[gout + i]      = h; Kl[gout + i]      = l;
        bsplit(k2*c + k1*sn, h, l); Kh[gout + i + 32] = h; Kl[gout + i + 32] = l;
    }
    #pragma unroll
    for (int u = 0; u < 16; u++) {
        const int idx = tid + u * 256;            // 64 t x 64 hd
        const int r = idx >> 6, cd = idx & 63;
        const float v = qkv[2*MH_ + (size_t)(b*T_ + t0 + r) * H_ + nh * HD_ + cd];
        __nv_bfloat16 h, l; bsplit(v, h, l);
        vh_s[cd][r] = h; vl_s[cd][r] = l;
    }
    __syncthreads();
    #pragma unroll
    for (int u = 0; u < 16; u++) {
        const int idx = tid + u * 256;
        const int hd = idx >> 6, tt = idx & 63;
        const size_t go = ((size_t)bh * HD_ + hd) * T_ + t0 + tt;
        Vh[go] = vh_s[hd][tt];
        Vl[go] = vl_s[hd][tt];
    }
}

// ---------------- tensor-core flash attention (bf16x3, causal) ----------------
// CTA = (qt, bh): 64 q rows, 4 warps x 16 rows. kv tiles of 64, 3-stage pipeline.
#define ATT_SMEM 114688   // Q hi/lo 16KB + 3 KV stages x 32KB

__global__ void __launch_bounds__(128)
attn_mma(const __nv_bfloat16* __restrict__ Qh, const __nv_bfloat16* __restrict__ Ql,
         const __nv_bfloat16* __restrict__ Kh, const __nv_bfloat16* __restrict__ Kl,
         const __nv_bfloat16* __restrict__ Vh, const __nv_bfloat16* __restrict__ Vl,
         __nv_bfloat16* __restrict__ att_hi, __nv_bfloat16* __restrict__ att_lo)
{
    extern __shared__ uint32_t smu[];
    const int qt = (int)gridDim.x - 1 - (int)blockIdx.x;   // long CTAs first
    const int bh = blockIdx.y;
    const int b = bh >> 4, nh = bh & 15;
    const int tid = threadIdx.x, lane = tid & 31, wid = tid >> 5;
    const int g = lane >> 2, tg = lane & 3, li = lane & 7;
    const int wrow = wid * 16;
    const uint32_t smb = s2u(smu);
    const uint32_t QLOF = 8192u, KVOF = 16384u;

    // load Q tile once (group 0)
    {
        const size_t gq = ((size_t)bh * T_ + qt * 64) * HD_;
        #pragma unroll
        for (int u = 0; u < 4; u++) {
            const int idx = tid + u * 128;
            const int r = idx >> 3, kc = idx & 7;
            const uint32_t sw = (uint32_t)(r * 128 + ((kc ^ (r & 7)) << 4));
            cpa16(smb + sw,        Qh + gq + (size_t)r * HD_ + kc * 8);
            cpa16(smb + QLOF + sw, Ql + gq + (size_t)r * HD_ + kc * 8);
        }
        cp_commit();
    }
    auto load_kv = [&](int st, int kvt) {
        const uint32_t base = smb + KVOF + (uint32_t)st * 32768u;
        const size_t gk = ((size_t)bh * T_ + kvt * 64) * HD_;
        const size_t gv = (size_t)bh * HD_ * T_ + kvt * 64;
        #pragma unroll
        for (int u = 0; u < 4; u++) {
            const int idx = tid + u * 128;
            const int r = idx >> 3, kc = idx & 7;
            const uint32_t sw = (uint32_t)(r * 128 + ((kc ^ (r & 7)) << 4));
            cpa16(base +          sw, Kh + gk + (size_t)r * HD_ + kc * 8);
            cpa16(base + 8192u  + sw, Kl + gk + (size_t)r * HD_ + kc * 8);
            cpa16(base + 16384u + sw, Vh + gv + (size_t)r * T_ + kc * 8);
            cpa16(base + 24576u + sw, Vl + gv + (size_t)r * T_ + kc * 8);
        }
        cp_commit();
    };

    float m0 = -1e30f, m1 = -1e30f, l0 = 0.f, l1 = 0.f;
    float Oacc[8][4];
    #pragma unroll
    for (int nt = 0; nt < 8; nt++)
        #pragma unroll
        for (int c = 0; c < 4; c++) Oacc[nt][c] = 0.f;

    const int nkv = qt + 1;
    load_kv(0, 0);
    if (nkv > 1) load_kv(1, 1);

    const uint32_t aRow  = (uint32_t)(wrow + li + ((lane >> 3) & 1) * 8);
    const uint32_t aKcS  = (uint32_t)(lane >> 4);
    const uint32_t bRow0 = (uint32_t)(li + ((lane >> 4) << 3));
    const uint32_t bKcS  = (uint32_t)((lane >> 3) & 1);

    for (int kvt = 0; kvt < nkv; kvt++) {
        const int st = kvt % 3;
        if (kvt + 1 < nkv) cp_wait<1>(); else cp_wait<0>();
        __syncthreads();
        if (kvt + 2 < nkv) load_kv((kvt + 2) % 3, kvt + 2);
        const uint32_t kbase = smb + KVOF + (uint32_t)st * 32768u;

        // ---- S = Q @ K^T (bf16x3) ----
        float sacc[8][4];
        #pragma unroll
        for (int nt = 0; nt < 8; nt++)
            #pragma unroll
            for (int c = 0; c < 4; c++) sacc[nt][c] = 0.f;

        #pragma unroll
        for (int ks = 0; ks < 4; ks++) {
            const uint32_t kcA = (uint32_t)(2 * ks) + aKcS;
            const uint32_t qaddr = smb + aRow * 128 + ((kcA ^ (aRow & 7)) << 4);
            uint32_t aH[4], aL[4];
            ldm_x4(aH, qaddr);
            ldm_x4(aL, qaddr + QLOF);
            const uint32_t kcB = (uint32_t)(2 * ks) + bKcS;
            uint32_t bH[8][2], bL[8][2];
            #pragma unroll
            for (int gg = 0; gg < 4; gg++) {
                const uint32_t rb = bRow0 + (uint32_t)(gg * 16);
                const uint32_t ad = kbase + rb * 128 + ((kcB ^ (rb & 7)) << 4);
                uint32_t r4[4];
                ldm_x4(r4, ad);
                bH[gg*2][0]=r4[0]; bH[gg*2][1]=r4[1]; bH[gg*2+1][0]=r4[2]; bH[gg*2+1][1]=r4[3];
                ldm_x4(r4, ad + 8192u);
                bL[gg*2][0]=r4[0]; bL[gg*2][1]=r4[1]; bL[gg*2+1][0]=r4[2]; bL[gg*2+1][1]=r4[3];
            }
            #pragma unroll
            for (int nt = 0; nt < 8; nt++) {
                mma16816(sacc[nt], aH, bH[nt]);
                mma16816(sacc[nt], aH, bL[nt]);
                mma16816(sacc[nt], aL, bH[nt]);
            }
        }

        // ---- scale + causal mask (only diagonal tile) ----
        if (kvt == qt) {
            const int r0 = wrow + g, r1 = r0 + 8;
            #pragma unroll
            for (int nt = 0; nt < 8; nt++) {
                const int c0 = nt * 8 + 2 * tg, c1 = c0 + 1;
                sacc[nt][0] = (c0 <= r0) ? sacc[nt][0] * 0.125f : -1e9f;
                sacc[nt][1] = (c1 <= r0) ? sacc[nt][1] * 0.125f : -1e9f;
                sacc[nt][2] = (c0 <= r1) ? sacc[nt][2] * 0.125f : -1e9f;
                sacc[nt][3] = (c1 <= r1) ? sacc[nt][3] * 0.125f : -1e9f;
            }
        } else {
            #pragma unroll
            for (int nt = 0; nt < 8; nt++)
                #pragma unroll
                for (int c = 0; c < 4; c++) sacc[nt][c] *= 0.125f;
        }

        // ---- online softmax (rows g and g+8; quad reduce over tg lanes) ----
        float mx0 = sacc[0][0], mx1 = sacc[0][2];
        #pragma unroll
        for (int nt = 0; nt < 8; nt++) {
            mx0 = fmaxf(mx0, fmaxf(sacc[nt][0], sacc[nt][1]));
            mx1 = fmaxf(mx1, fmaxf(sacc[nt][2], sacc[nt][3]));
        }
        mx0 = fmaxf(mx0, __shfl_xor_sync(0xffffffffu, mx0, 1));
        mx0 = fmaxf(mx0, __shfl_xor_sync(0xffffffffu, mx0, 2));
        mx1 = fmaxf(mx1, __shfl_xor_sync(0xffffffffu, mx1, 1));
        mx1 = fmaxf(mx1, __shfl_xor_sync(0xffffffffu, mx1, 2));
        const float mn0 = fmaxf(m0, mx0), mn1 = fmaxf(m1, mx1);
        const float al0 = __expf(m0 - mn0), al1 = __expf(m1 - mn1);
        float rs0 = 0.f, rs1 = 0.f;
        #pragma unroll
        for (int nt = 0; nt < 8; nt++) {
            sacc[nt][0] = __expf(sacc[nt][0] - mn0); rs0 += sacc[nt][0];
            sacc[nt][1] = __expf(sacc[nt][1] - mn0); rs0 += sacc[nt][1];
            sacc[nt][2] = __expf(sacc[nt][2] - mn1); rs1 += sacc[nt][2];
            sacc[nt][3] = __expf(sacc[nt][3] - mn1); rs1 += sacc[nt][3];
        }
        rs0 += __shfl_xor_sync(0xffffffffu, rs0, 1);
        rs0 += __shfl_xor_sync(0xffffffffu, rs0, 2);
        rs1 += __shfl_xor_sync(0xffffffffu, rs1, 1);
        rs1 += __shfl_xor_sync(0xffffffffu, rs1, 2);
        l0 = l0 * al0 + rs0; l1 = l1 * al1 + rs1;
        m0 = mn0; m1 = mn1;
        #pragma unroll
        for (int nt = 0; nt < 8; nt++) {
            Oacc[nt][0] *= al0; Oacc[nt][1] *= al0;
            Oacc[nt][2] *= al1; Oacc[nt][3] *= al1;
        }

        // ---- O += P @ V^T (P fragments come straight from S accumulators) ----
        const uint32_t vbase = kbase + 16384u;
        #pragma unroll
        for (int ks = 0; ks < 4; ks++) {
            const int j0 = 2 * ks, j1 = j0 + 1;
            float r00, r01, r02, r03, r10, r11, r12, r13;
            uint32_t aPh[4], aPl[4];
            aPh[0] = pack_hi(sacc[j0][0], sacc[j0][1], r00, r01);
            aPh[1] = pack_hi(sacc[j0][2], sacc[j0][3], r02, r03);
            aPh[2] = pack_hi(sacc[j1][0], sacc[j1][1], r10, r11);
            aPh[3] = pack_hi(sacc[j1][2], sacc[j1][3], r12, r13);
            aPl[0] = pack_lo(r00, r01); aPl[1] = pack_lo(r02, r03);
            aPl[2] = pack_lo(r10, r11); aPl[3] = pack_lo(r12, r13);
            const uint32_t kcV = (uint32_t)(2 * ks) + bKcS;
            uint32_t vH[8][2], vL[8][2];
            #pragma unroll
            for (int gg = 0; gg < 4; gg++) {
                const uint32_t rb = bRow0 + (uint32_t)(gg * 16);
                const uint32_t ad = vbase + rb * 128 + ((kcV ^ (rb & 7)) << 4);
                uint32_t r4[4];
                ldm_x4(r4, ad);
                vH[gg*2][0]=r4[0]; vH[gg*2][1]=r4[1]; vH[gg*2+1][0]=r4[2]; vH[gg*2+1][1]=r4[3];
                ldm_x4(r4, ad + 8192u);
                vL[gg*2][0]=r4[0]; vL[gg*2][1]=r4[1]; vL[gg*2+1][0]=r4[2]; vL[gg*2+1][1]=r4[3];
            }
            #pragma unroll
            for (int nt = 0; nt < 8; nt++) {
                mma16816(Oacc[nt], aPh, vH[nt]);
                mma16816(Oacc[nt], aPh, vL[nt]);
                mma16816(Oacc[nt], aPl, vH[nt]);
            }
        }
        // no trailing sync: 3-stage pipeline, same proof as gemm
    }

    // ---- epilogue: O/l -> att hi/lo [M][H] ----
    const float i0 = 1.f / l0, i1 = 1.f / l1;
    const int trow = qt * 64 + wrow + g;
    const size_t mrow0 = (size_t)(b * T_ + trow) * H_ + nh * HD_;
    const size_t mrow1 = mrow0 + (size_t)8 * H_;
    #pragma unroll
    for (int nt = 0; nt < 8; nt++) {
        const int col = nt * 8 + 2 * tg;
        __nv_bfloat16 h, l;
        float v;
        v = Oacc[nt][0] * i0; bsplit(v, h, l); att_hi[mrow0+col]   = h; att_lo[mrow0+col]   = l;
        v = Oacc[nt][1] * i0; bsplit(v, h, l); att_hi[mrow0+col+1] = h; att_lo[mrow0+col+1] = l;
        v = Oacc[nt][2] * i1; bsplit(v, h, l); att_hi[mrow1+col]   = h; att_lo[mrow1+col]   = l;
        v = Oacc[nt][3] * i1; bsplit(v, h, l); att_hi[mrow1+col+1] = h; att_lo[mrow1+col+1] = l;
    }
}

// ---------------- SwiGLU: act = silu(g) * u -> bf16 hi/lo ----------------
__global__ void silu_kernel(const float* __restrict__ g, const float* __restrict__ u,
                            __nv_bfloat16* __restrict__ ahi, __nv_bfloat16* __restrict__ alo,
                            int n) {
    const int i = blockIdx.x*256 + threadIdx.x;
    if (i < n) {
        const float gv = g[i];
        float v = (gv / (1.0f + expf(-gv))) * u[i];
        __nv_bfloat16 h, l; bsplit(v, h, l);
        ahi[i] = h; alo[i] = l;
    }
}

// ---------------- head: logits = latent@W + b, clamp, softmax ----------------
__global__ void head_kernel(const float* __restrict__ latent, const float* __restrict__ W,
                            const float* __restrict__ bias, const float* __restrict__ temp,
                            float* __restrict__ out) {
    const int m = blockIdx.x;
    __shared__ float xs[H_];
    __shared__ float red[8][32];
    const float* row = latent + (size_t)m*H_;
    for (int i = threadIdx.x; i < H_; i += 256) xs[i] = row[i];
    __syncthreads();
    const int n  = threadIdx.x & 31;
    const int ch = threadIdx.x >> 5;
    float p = 0.f;
    if (n < 31) {
        const int k0 = ch*128;
        for (int k = k0; k < k0 + 128; k++) p += xs[k]*W[(size_t)k*31 + n];
    }
    red[ch][n] = p;
    __syncthreads();
    if (threadIdx.x < 32) {
        float v = 0.f;
        if (n < 31) {
            #pragma unroll
            for (int c = 0; c < 8; c++) v += red[c][n];
            v += bias[n];
            v = fminf(fmaxf(v, -10.0f), 10.0f);
            out[(size_t)M_*31 + (size_t)m*31 + n] = v;
        }
        const float t = *temp;
        float mx = (n < 31) ? v : -1e30f;
        #pragma unroll
        for (int o = 16; o; o >>= 1) mx = fmaxf(mx, __shfl_xor_sync(0xffffffffu, mx, o));
        const float ev = (n < 31) ? expf((v - mx)/t) : 0.f;
        float sm = ev;
        #pragma unroll
        for (int o = 16; o; o >>= 1) sm += __shfl_xor_sync(0xffffffffu, sm, o);
        if (n < 31) out[(size_t)m*31 + n] = ev/sm;
    }
}

// ---------------- launcher ----------------
extern "C" void kernel_launch(void* const* d_in, const int* in_sizes, int n_in,
                              void* d_out, int out_size) {
    (void)in_sizes; (void)n_in; (void)out_size;
    const float* x       = (const float*)d_in[0];
    const float* temp    = (const float*)d_in[1];
    const float* state_W = (const float*)d_in[2];
    const float* state_b = (const float*)d_in[3];
    const float* ln1     = (const float*)d_in[4];
    const float* ln2     = (const float*)d_in[5];
    const float* Wqkv    = (const float*)d_in[6];
    const float* Aqkv    = (const float*)d_in[7];
    const float* Bqkv    = (const float*)d_in[8];
    const float* Wo      = (const float*)d_in[9];
    const float* Ao      = (const float*)d_in[10];
    const float* Bo      = (const float*)d_in[11];
    const float* Wgu     = (const float*)d_in[12];
    const float* Agu     = (const float*)d_in[13];
    const float* Bgu     = (const float*)d_in[14];
    const float* Wd      = (const float*)d_in[15];
    const float* Ad      = (const float*)d_in[16];
    const float* Bd      = (const float*)d_in[17];
    const float* ln_f    = (const float*)d_in[18];
    const float* head_W  = (const float*)d_in[19];
    const float* head_b  = (const float*)d_in[20];
    float* out = (float*)d_out;

    float *p_h, *p_hn, *p_qkv, *p_gu;
    __nv_bfloat16 *p_hn_hi, *p_hn_lo, *p_att_hi, *p_att_lo, *p_act_hi, *p_act_lo;
    __nv_bfloat16 *pq_hi, *pq_lo, *pk_hi, *pk_lo, *pv_hi, *pv_lo;
    __nv_bfloat16 *pWq_hi, *pWq_lo, *pWo_hi, *pWo_lo, *pWgu_hi, *pWgu_lo, *pWd_hi, *pWd_lo;
    cudaGetSymbolAddress((void**)&p_h,     g_h);
    cudaGetSymbolAddress((void**)&p_hn,    g_hn);
    cudaGetSymbolAddress((void**)&p_qkv,   g_qkv);
    cudaGetSymbolAddress((void**)&p_gu,    g_gu);
    cudaGetSymbolAddress((void**)&p_hn_hi, g_hn_hi);
    cudaGetSymbolAddress((void**)&p_hn_lo, g_hn_lo);
    cudaGetSymbolAddress((void**)&p_att_hi,g_att_hi);
    cudaGetSymbolAddress((void**)&p_att_lo,g_att_lo);
    cudaGetSymbolAddress((void**)&p_act_hi,g_act_hi);
    cudaGetSymbolAddress((void**)&p_act_lo,g_act_lo);
    cudaGetSymbolAddress((void**)&pq_hi,   g_qr_hi);
    cudaGetSymbolAddress((void**)&pq_lo,   g_qr_lo);
    cudaGetSymbolAddress((void**)&pk_hi,   g_kr_hi);
    cudaGetSymbolAddress((void**)&pk_lo,   g_kr_lo);
    cudaGetSymbolAddress((void**)&pv_hi,   g_vt_hi);
    cudaGetSymbolAddress((void**)&pv_lo,   g_vt_lo);
    cudaGetSymbolAddress((void**)&pWq_hi,  g_Wq_hi);
    cudaGetSymbolAddress((void**)&pWq_lo,  g_Wq_lo);
    cudaGetSymbolAddress((void**)&pWo_hi,  g_Wo_hi);
    cudaGetSymbolAddress((void**)&pWo_lo,  g_Wo_lo);
    cudaGetSymbolAddress((void**)&pWgu_hi, g_Wgu_hi);
    cudaGetSymbolAddress((void**)&pWgu_lo, g_Wgu_lo);
    cudaGetSymbolAddress((void**)&pWd_hi,  g_Wd_hi);
    cudaGetSymbolAddress((void**)&pWd_lo,  g_Wd_lo);

    cudaFuncSetAttribute(gemm_bf16x3, cudaFuncAttributeMaxDynamicSharedMemorySize, GSMEM_BYTES);
    cudaFuncSetAttribute(attn_mma,    cudaFuncAttributeMaxDynamicSharedMemorySize, ATT_SMEM);

    // ---- fold LoRA + transpose + bf16-split effective weights ----
    fold_kernel<<<dim3(32, 32, 24), 256>>>(Wqkv, Aqkv, Bqkv, pWq_hi,  pWq_lo,  H_, H_);
    fold_kernel<<<dim3(32, 32,  8), 256>>>(Wo,   Ao,   Bo,   pWo_hi,  pWo_lo,  H_, H_);
    fold_kernel<<<dim3(32, 88, 16), 256>>>(Wgu,  Agu,  Bgu,  pWgu_hi, pWgu_lo, H_, F_);
    fold_kernel<<<dim3(88, 32,  8), 256>>>(Wd,   Ad,   Bd,   pWd_hi,  pWd_lo,  F_, H_);

    // ---- embed + first rms ----
    init_h_kernel<<<dim3(4, M_), 256>>>(x, state_W, state_b);
    rms_kernel<<<M_, 256>>>(p_h, ln1, p_hn, p_hn_hi, p_hn_lo);

    // ---- layers ----
    for (int l = 0; l < L_; l++) {
        gemm_bf16x3<<<dim3(8, 16, 3), 128, GSMEM_BYTES>>>(
            p_hn_hi, p_hn_lo, pWq_hi + (size_t)l*3*HH_, pWq_lo + (size_t)l*3*HH_,
            p_qkv, H_, H_, H_, HH_, MH_, 0);
        qkv_prep<<<dim3(16, 16, 2), 256>>>(p_qkv, pq_hi, pq_lo, pk_hi, pk_lo, pv_hi, pv_lo);
        attn_mma<<<dim3(16, 32), 128, ATT_SMEM>>>(pq_hi, pq_lo, pk_hi, pk_lo, pv_hi, pv_lo,
                                                  p_att_hi, p_att_lo);
        gemm_bf16x3<<<dim3(8, 16, 2), 128, GSMEM_BYTES>>>(
            p_att_hi, p_att_lo, pWo_hi + (size_t)l*HH_, pWo_lo + (size_t)l*HH_,
            p_qkv, H_, 512, H_, 0, MH_, 512);
        rms3_kernel<<<M_, 256>>>(p_h, p_qkv, p_qkv + MH_, ln2 + (size_t)l*H_,
                                 p_hn, p_hn_hi, p_hn_lo);
        gemm_bf16x3<<<dim3(22, 16, 2), 128, GSMEM_BYTES>>>(
            p_hn_hi, p_hn_lo, pWgu_hi + (size_t)l*2*HF_, pWgu_lo + (size_t)l*2*HF_,
            p_gu, F_, H_, H_, HF_, MF_, 0);
        silu_kernel<<<(int)((MF_ + 255)/256), 256>>>(p_gu, p_gu + MF_, p_act_hi, p_act_lo, (int)MF_);
        gemm_bf16x3<<<dim3(8, 16, 2), 128, GSMEM_BYTES>>>(
            p_act_hi, p_act_lo, pWd_hi + (size_t)l*HF_, pWd_lo + (size_t)l*HF_,
            p_gu, H_, 1408, F_, 0, MH_, 1408);
        const float* wnext = (l < L_-1) ? (ln1 + (size_t)(l+1)*H_) : ln_f;
        rms3_kernel<<<M_, 256>>>(p_h, p_gu, p_gu + MH_, wnext,
                                 p_hn, p_hn_hi, p_hn_lo);
    }

    // ---- head + softmax ----
    head_kernel<<<M_, 256>>>(p_hn, head_W, head_b, temp, out);
}